// round 15
// baseline (speedup 1.0000x reference)
#include <cuda_runtime.h>
#include <cuda_bf16.h>
#include <cstdint>

#define N_NODES 50000
#define E_EDGES 400000
#define E_TOT   450000
#define G_GRAPHS 256
#define HC 200
#define C_CH 100
#define F_IN 336
#define SLOPE 0.2f
#define NB_SCAN 49
#define K2_IN  168     // F_IN/2 pairs
#define K2_HID 100     // HC/2 pairs
#define W_ST   168     // weight plane stride (pairs)

// ---------------- scratch -----------------------------------------------------
__device__ float g_x[N_NODES * HC];
__device__ float g_h[N_NODES * HC];
__device__ uint32_t g_xh336[N_NODES * K2_IN];
__device__ uint32_t g_xl336[N_NODES * K2_IN];
__device__ uint32_t g_ah[N_NODES * K2_HID];
__device__ uint32_t g_al[N_NODES * K2_HID];
__device__ uint32_t g_wh[5 * HC * W_ST];
__device__ uint32_t g_wl[5 * HC * W_ST];
__device__ float g_es[N_NODES * 2];
__device__ float g_ed[N_NODES * 2];
__device__ float g_alpha[E_TOT * 2];
__device__ int   g_cnt[N_NODES];
__device__ int   g_rowptr[N_NODES + 1];
__device__ int   g_wr[N_NODES];
__device__ int   g_srcidx[E_TOT];
__device__ int   g_bsum[NB_SCAN];
__device__ float g_pool[G_GRAPHS * HC];
__device__ int   g_pcnt[G_GRAPHS];
__device__ float g_t1[G_GRAPHS * 100];
__device__ float g_t2[G_GRAPHS * 100];

// ---------------- bf16 split helpers ------------------------------------------
__device__ __forceinline__ uint32_t pack_bf16(float lo_e, float hi_e) {
    uint32_t u;
    asm("cvt.rn.bf16x2.f32 %0, %1, %2;" : "=r"(u) : "f"(hi_e), "f"(lo_e));
    return u;
}
__device__ __forceinline__ float bf16lo_f(uint32_t u) { return __uint_as_float(u << 16); }
__device__ __forceinline__ float bf16hi_f(uint32_t u) { return __uint_as_float(u & 0xFFFF0000u); }
__device__ __forceinline__ void split_pair(float x0, float x1, uint32_t& hi, uint32_t& lo) {
    hi = pack_bf16(x0, x1);
    float r0 = x0 - bf16lo_f(hi);
    float r1 = x1 - bf16hi_f(hi);
    lo = pack_bf16(r0, r1);
}

// ---------------- operand pre-split kernels ------------------------------------
__global__ void k_splitX(const float* __restrict__ x) {
    long i = (long)blockIdx.x * blockDim.x + threadIdx.x;
    if (i >= (long)N_NODES * K2_IN) return;
    int n = (int)(i / K2_IN), p = (int)(i % K2_IN);
    float2 v = *(const float2*)(x + (long)n * F_IN + 2 * p);
    uint32_t h, l;
    split_pair(v.x, v.y, h, l);
    g_xh336[i] = h; g_xl336[i] = l;
}

__global__ void k_splitW(const float* __restrict__ W0, const float* __restrict__ W1,
                         const float* __restrict__ W2, const float* __restrict__ W3,
                         const float* __restrict__ W4) {
    int i = blockIdx.x * blockDim.x + threadIdx.x;
    if (i >= 5 * HC * W_ST) return;
    int l = i / (HC * W_ST);
    int rem = i - l * (HC * W_ST);
    int n = rem / W_ST, p = rem % W_ST;
    int K = (l == 0) ? F_IN : HC;
    uint32_t h = 0, lo = 0;
    if (2 * p < K) {
        const float* W = (l == 0) ? W0 : (l == 1) ? W1 : (l == 2) ? W2 : (l == 3) ? W3 : W4;
        float a = W[(2 * p) * HC + n];
        float b = W[(2 * p + 1) * HC + n];
        split_pair(a, b, h, lo);
    }
    g_wh[i] = h; g_wl[i] = lo;
}

// ---------------- CSR build ---------------------------------------------------
__global__ void k_init_cnt() {
    int i = blockIdx.x * blockDim.x + threadIdx.x;
    if (i < N_NODES) g_cnt[i] = 1;
    if (i < G_GRAPHS) g_pcnt[i] = 0;
    if (i < G_GRAPHS * HC) g_pool[i] = 0.f;
}

__global__ void k_count(const int* __restrict__ ei) {
    int e = blockIdx.x * blockDim.x + threadIdx.x;
    if (e < E_EDGES) atomicAdd(&g_cnt[ei[E_EDGES + e]], 1);
}

__global__ void k_pcnt(const int* __restrict__ batch) {
    int i = blockIdx.x * blockDim.x + threadIdx.x;
    if (i < N_NODES) atomicAdd(&g_pcnt[batch[i]], 1);
}

__global__ void k_bsum() {
    __shared__ int sh[256];
    int b = blockIdx.x, t = threadIdx.x;
    int base = b * 1024;
    int s = 0;
#pragma unroll
    for (int j = 0; j < 4; j++) {
        int i = base + t + j * 256;
        if (i < N_NODES) s += g_cnt[i];
    }
    sh[t] = s; __syncthreads();
    for (int off = 128; off; off >>= 1) {
        if (t < off) sh[t] += sh[t + off];
        __syncthreads();
    }
    if (t == 0) g_bsum[b] = sh[0];
}

__global__ void k_bscan() {
    if (threadIdx.x == 0) {
        int run = 0;
        for (int b = 0; b < NB_SCAN; b++) { int v = g_bsum[b]; g_bsum[b] = run; run += v; }
    }
}

__global__ void k_rowptr() {
    __shared__ int sh[256];
    int b = blockIdx.x, t = threadIdx.x;
    int i0 = b * 1024 + t * 4;
    int c[4]; int local = 0;
#pragma unroll
    for (int j = 0; j < 4; j++) {
        int i = i0 + j;
        c[j] = (i < N_NODES) ? g_cnt[i] : 0;
        local += c[j];
    }
    sh[t] = local; __syncthreads();
    for (int off = 1; off < 256; off <<= 1) {
        int v = (t >= off) ? sh[t - off] : 0;
        __syncthreads();
        sh[t] += v;
        __syncthreads();
    }
    int run = g_bsum[b] + sh[t] - local;
#pragma unroll
    for (int j = 0; j < 4; j++) {
        int i = i0 + j;
        if (i < N_NODES) { g_rowptr[i] = run; g_wr[i] = run; run += c[j]; }
    }
    if (b == 0 && t == 0) g_rowptr[N_NODES] = E_TOT;
}

__global__ void k_scatter(const int* __restrict__ ei) {
    int e = blockIdx.x * blockDim.x + threadIdx.x;
    if (e >= E_TOT) return;
    int s, d;
    if (e < E_EDGES) { s = ei[e]; d = ei[E_EDGES + e]; }
    else             { s = d = e - E_EDGES; }
    int pos = atomicAdd(&g_wr[d], 1);
    g_srcidx[pos] = s;
}

// ---------------- BM=256 pre-split bf16x3 GEMM, 2 CTAs/SM ----------------------
__device__ __forceinline__ void mma_bf16(float* c, const uint32_t* a, const uint32_t* b) {
    asm volatile(
        "mma.sync.aligned.m16n8k16.row.col.f32.bf16.bf16.f32 "
        "{%0,%1,%2,%3},{%4,%5,%6,%7},{%8,%9},{%0,%1,%2,%3};"
        : "+f"(c[0]), "+f"(c[1]), "+f"(c[2]), "+f"(c[3])
        : "r"(a[0]), "r"(a[1]), "r"(a[2]), "r"(a[3]), "r"(b[0]), "r"(b[1]));
}

__device__ __forceinline__ void ldm_x4(uint32_t& r0, uint32_t& r1, uint32_t& r2,
                                       uint32_t& r3, uint32_t addr) {
    asm volatile("ldmatrix.sync.aligned.m8n8.x4.shared.b16 {%0,%1,%2,%3}, [%4];"
                 : "=r"(r0), "=r"(r1), "=r"(r2), "=r"(r3) : "r"(addr));
}

__device__ __forceinline__ void cpa16(uint32_t dst, const uint32_t* src, int bytes) {
    asm volatile("cp.async.ca.shared.global [%0], [%1], 16, %2;\n"
                 :: "r"(dst), "l"(src), "r"(bytes));
}

#define PST 20                         // uint32 per smem row (80B), ldmatrix conflict-free
#define AH_U 0
#define AL_U (256 * PST)
#define BH_U (2 * 256 * PST)
#define BL_U (BH_U + 64 * PST)
#define BUF_U (BL_U + 64 * PST)        // 12800 uint32 = 51200 B
#define GEMM_SMEM (2 * BUF_U * 4)      // 102400 B

__global__ void __launch_bounds__(256, 2)
k_gemm_pre(const uint32_t* __restrict__ AH, const uint32_t* __restrict__ AL, int sA,
           const uint32_t* __restrict__ BH, const uint32_t* __restrict__ BL, int sB,
           float* __restrict__ C, int M, int K2, int Nn)
{
    extern __shared__ __align__(16) uint32_t smn[];
    uint32_t sbase = (uint32_t)__cvta_generic_to_shared(smn);

    int tid = threadIdx.x;
    int rowBase = blockIdx.y * 256;
    int colBase = blockIdx.x * 64;
    int warpId = tid >> 5, lane = tid & 31;
    int wm = warpId * 32;
    int gr = lane >> 2;
    int cq = lane & 3;
    int lrow = lane & 15;
    int lcol = (lane >> 4) * 4;

    float acc[2][8][4];
#pragma unroll
    for (int i = 0; i < 2; i++)
#pragma unroll
        for (int j = 0; j < 8; j++)
#pragma unroll
            for (int k = 0; k < 4; k++) acc[i][j][k] = 0.f;

    int srow = tid >> 2;                // 0..63
    int schk = (tid & 3) * 4;           // pair offset 0,4,8,12

    int ntiles = (K2 + 15) / 16;

    auto stage = [&](int t) {
        int k2b = t * 16;
        uint32_t bb = sbase + (uint32_t)(t & 1) * (BUF_U * 4);
        int kp = k2b + schk;
        int remk = K2 - kp;
        int okk = remk >= 4 ? 16 : (remk > 0 ? remk * 4 : 0);
#pragma unroll
        for (int i = 0; i < 4; i++) {
            int row = srow + i * 64;
            int bytes = ((rowBase + row) < M) ? okk : 0;
            uint32_t d = bb + (uint32_t)(row * PST + schk) * 4;
            cpa16(d + AH_U * 4, AH + (long)(rowBase + row) * sA + kp, bytes);
            cpa16(d + AL_U * 4, AL + (long)(rowBase + row) * sA + kp, bytes);
        }
        {
            int bytes = ((colBase + srow) < Nn) ? okk : 0;
            uint32_t d = bb + (uint32_t)(srow * PST + schk) * 4;
            cpa16(d + BH_U * 4, BH + (long)(colBase + srow) * sB + kp, bytes);
            cpa16(d + BL_U * 4, BL + (long)(colBase + srow) * sB + kp, bytes);
        }
        asm volatile("cp.async.commit_group;\n");
    };

    stage(0);

    for (int t = 0; t < ntiles; t++) {
        if (t + 1 < ntiles) {
            stage(t + 1);
            asm volatile("cp.async.wait_group 1;\n");
        } else {
            asm volatile("cp.async.wait_group 0;\n");
        }
        __syncthreads();

        uint32_t bb = sbase + (uint32_t)(t & 1) * (BUF_U * 4);
#pragma unroll
        for (int ks = 0; ks < 2; ks++) {
            int kc = ks * 8 + lcol;
            uint32_t ah[2][4], al_[2][4];
#pragma unroll
            for (int mt = 0; mt < 2; mt++) {
                uint32_t off = (uint32_t)((wm + mt * 16 + lrow) * PST + kc) * 4;
                ldm_x4(ah[mt][0], ah[mt][1], ah[mt][2], ah[mt][3], bb + AH_U * 4 + off);
                ldm_x4(al_[mt][0], al_[mt][1], al_[mt][2], al_[mt][3], bb + AL_U * 4 + off);
            }
            // process B in chunks of 4 n-tiles to cap register usage (fits 2 CTAs/SM)
#pragma unroll
            for (int half = 0; half < 2; half++) {
                uint32_t bh[4][2], bl[4][2];
                {
                    uint32_t off = (uint32_t)((half * 32 + lrow) * PST + kc) * 4;
                    uint32_t t0, t1, t2, t3;
                    ldm_x4(t0, t1, t2, t3, bb + BH_U * 4 + off);
                    bh[0][0] = t0; bh[0][1] = t2;
                    bh[1][0] = t1; bh[1][1] = t3;
                    ldm_x4(t0, t1, t2, t3, bb + BL_U * 4 + off);
                    bl[0][0] = t0; bl[0][1] = t2;
                    bl[1][0] = t1; bl[1][1] = t3;
                }
                {
                    uint32_t off = (uint32_t)((half * 32 + 16 + lrow) * PST + kc) * 4;
                    uint32_t t0, t1, t2, t3;
                    ldm_x4(t0, t1, t2, t3, bb + BH_U * 4 + off);
                    bh[2][0] = t0; bh[2][1] = t2;
                    bh[3][0] = t1; bh[3][1] = t3;
                    ldm_x4(t0, t1, t2, t3, bb + BL_U * 4 + off);
                    bl[2][0] = t0; bl[2][1] = t2;
                    bl[3][0] = t1; bl[3][1] = t3;
                }
#pragma unroll
                for (int mt = 0; mt < 2; mt++)
#pragma unroll
                    for (int q = 0; q < 4; q++) {
                        float* c = acc[mt][half * 4 + q];
                        mma_bf16(c, al_[mt], bh[q]);
                        mma_bf16(c, ah[mt], bl[q]);
                        mma_bf16(c, ah[mt], bh[q]);
                    }
            }
        }
        __syncthreads();
    }

#pragma unroll
    for (int mt = 0; mt < 2; mt++) {
#pragma unroll
        for (int nt = 0; nt < 8; nt++) {
            int row = rowBase + wm + mt * 16 + gr;
            int col = colBase + nt * 8 + cq * 2;
            float* c = acc[mt][nt];
            if (col < Nn) {
                if (row < M)
                    *(float2*)(C + (long)row * Nn + col) = make_float2(c[0], c[1]);
                if (row + 8 < M)
                    *(float2*)(C + (long)(row + 8) * Nn + col) = make_float2(c[2], c[3]);
            }
        }
    }
}

// ---------------- attention scores (warp per node) -----------------------------
__global__ void k_scores(const float* __restrict__ asrc, const float* __restrict__ adst) {
    int gwarp = (blockIdx.x * blockDim.x + threadIdx.x) >> 5;
    int lane  = threadIdx.x & 31;
    if (gwarp >= N_NODES) return;
    const float* hr = g_h + (long)gwarp * HC;
    float es0 = 0.f, es1 = 0.f, ed0 = 0.f, ed1 = 0.f;
    for (int c = lane; c < HC; c += 32) {
        float v = hr[c], a = asrc[c], d = adst[c];
        if (c < C_CH) { es0 += v * a; ed0 += v * d; }
        else          { es1 += v * a; ed1 += v * d; }
    }
#pragma unroll
    for (int o = 16; o; o >>= 1) {
        es0 += __shfl_xor_sync(0xffffffffu, es0, o);
        es1 += __shfl_xor_sync(0xffffffffu, es1, o);
        ed0 += __shfl_xor_sync(0xffffffffu, ed0, o);
        ed1 += __shfl_xor_sync(0xffffffffu, ed1, o);
    }
    if (lane == 0) {
        g_es[gwarp * 2]     = es0;
        g_es[gwarp * 2 + 1] = es1;
        g_ed[gwarp * 2]     = ed0;
        g_ed[gwarp * 2 + 1] = ed1;
    }
}

// ---------------- softmax + aggregate (+ plane-split output) -------------------
__device__ __forceinline__ float lrelu(float e) { return e > 0.f ? e : SLOPE * e; }

__global__ void k_aggregate(const float* __restrict__ bc, int last) {
    int gwarp = (blockIdx.x * blockDim.x + threadIdx.x) >> 5;
    int lane  = threadIdx.x & 31;
    if (gwarp >= N_NODES) return;
    int dst = gwarp;
    int beg = g_rowptr[dst], end = g_rowptr[dst + 1];
    float ed0 = g_ed[dst * 2], ed1 = g_ed[dst * 2 + 1];

    float m0 = -1e30f, m1 = -1e30f;
    for (int i = beg + lane; i < end; i += 32) {
        int s = g_srcidx[i];
        m0 = fmaxf(m0, lrelu(g_es[s * 2]     + ed0));
        m1 = fmaxf(m1, lrelu(g_es[s * 2 + 1] + ed1));
    }
#pragma unroll
    for (int o = 16; o; o >>= 1) {
        m0 = fmaxf(m0, __shfl_xor_sync(0xffffffffu, m0, o));
        m1 = fmaxf(m1, __shfl_xor_sync(0xffffffffu, m1, o));
    }

    float s0 = 0.f, s1 = 0.f;
    for (int i = beg + lane; i < end; i += 32) {
        int s = g_srcidx[i];
        float p0 = __expf(lrelu(g_es[s * 2]     + ed0) - m0);
        float p1 = __expf(lrelu(g_es[s * 2 + 1] + ed1) - m1);
        g_alpha[i * 2]     = p0;
        g_alpha[i * 2 + 1] = p1;
        s0 += p0; s1 += p1;
    }
#pragma unroll
    for (int o = 16; o; o >>= 1) {
        s0 += __shfl_xor_sync(0xffffffffu, s0, o);
        s1 += __shfl_xor_sync(0xffffffffu, s1, o);
    }
    float inv0 = 1.f / (s0 + 1e-16f);
    float inv1 = 1.f / (s1 + 1e-16f);

    float2 acc2[4];
#pragma unroll
    for (int k = 0; k < 4; k++) acc2[k] = make_float2(0.f, 0.f);

    for (int i = beg; i < end; i++) {
        int s = g_srcidx[i];
        float a0 = g_alpha[i * 2]     * inv0;
        float a1 = g_alpha[i * 2 + 1] * inv1;
        const float2* hr = (const float2*)(g_h + (long)s * HC);
#pragma unroll
        for (int k = 0; k < 4; k++) {
            int p = lane + k * 32;
            if (p < K2_HID) {
                float2 v = hr[p];
                float a = (p < 50) ? a0 : a1;
                acc2[k].x += a * v.x;
                acc2[k].y += a * v.y;
            }
        }
    }

#pragma unroll
    for (int k = 0; k < 4; k++) {
        int p = lane + k * 32;
        if (p < K2_HID) {
            float2 b = ((const float2*)bc)[p];
            float o0 = fmaxf(acc2[k].x + b.x, 0.f);
            float o1 = fmaxf(acc2[k].y + b.y, 0.f);
            if (last) {
                *(float2*)(g_x + (long)dst * HC + 2 * p) = make_float2(o0, o1);
            } else {
                uint32_t h, l;
                split_pair(o0, o1, h, l);
                g_ah[(long)dst * K2_HID + p] = h;
                g_al[(long)dst * K2_HID + p] = l;
            }
        }
    }
}

// ---------------- mean pool ----------------------------------------------------
__global__ void k_pool(const int* __restrict__ batch) {
    int i = blockIdx.x * blockDim.x + threadIdx.x;
    if (i >= N_NODES * HC) return;
    int n = i / HC, c = i - n * HC;
    int b = batch[n];
    atomicAdd(&g_pool[b * HC + c], g_x[i]);
}

// ---------------- tiny MLP layer -----------------------------------------------
__global__ void k_mlp(const float* __restrict__ A, const float* __restrict__ Wm,
                      const float* __restrict__ bm, float* __restrict__ out,
                      int K, int Nn, int do_relu, int do_div) {
    int g = blockIdx.x;
    __shared__ float arow[HC];
    float inv = 1.f;
    if (do_div) inv = 1.f / fmaxf((float)g_pcnt[g], 1.f);
    for (int i = threadIdx.x; i < K; i += blockDim.x) arow[i] = A[g * K + i] * inv;
    __syncthreads();
    for (int j = threadIdx.x; j < Nn; j += blockDim.x) {
        float acc = bm[j];
        for (int k = 0; k < K; k++) acc += arow[k] * Wm[k * Nn + j];
        if (do_relu) acc = fmaxf(acc, 0.f);
        out[g * Nn + j] = acc;
    }
}

// ---------------- launch --------------------------------------------------------
extern "C" void kernel_launch(void* const* d_in, const int* in_sizes, int n_in,
                              void* d_out, int out_size) {
    const float* x    = (const float*)d_in[0];
    const int*   ei   = (const int*)d_in[1];
    const int*   batch= (const int*)d_in[2];
    const float *W[5], *as_[5], *ad_[5], *bc_[5];
    for (int i = 0; i < 5; i++) {
        W[i]   = (const float*)d_in[3 + 4 * i];
        as_[i] = (const float*)d_in[4 + 4 * i];
        ad_[i] = (const float*)d_in[5 + 4 * i];
        bc_[i] = (const float*)d_in[6 + 4 * i];
    }
    const float* lw1 = (const float*)d_in[23];
    const float* lb1 = (const float*)d_in[24];
    const float* lw2 = (const float*)d_in[25];
    const float* lb2 = (const float*)d_in[26];
    const float* lw3 = (const float*)d_in[27];
    const float* lb3 = (const float*)d_in[28];

    float *ph, *ppool, *pt1, *pt2;
    uint32_t *pxh, *pxl, *pah, *pal, *pwh, *pwl;
    cudaGetSymbolAddress((void**)&ph, g_h);
    cudaGetSymbolAddress((void**)&ppool, g_pool);
    cudaGetSymbolAddress((void**)&pt1, g_t1);
    cudaGetSymbolAddress((void**)&pt2, g_t2);
    cudaGetSymbolAddress((void**)&pxh, g_xh336);
    cudaGetSymbolAddress((void**)&pxl, g_xl336);
    cudaGetSymbolAddress((void**)&pah, g_ah);
    cudaGetSymbolAddress((void**)&pal, g_al);
    cudaGetSymbolAddress((void**)&pwh, g_wh);
    cudaGetSymbolAddress((void**)&pwl, g_wl);

    static int smem_set = 0;
    if (!smem_set) {
        cudaFuncSetAttribute(k_gemm_pre, cudaFuncAttributeMaxDynamicSharedMemorySize,
                             GEMM_SMEM);
        smem_set = 1;
    }

    dim3 tg((HC + 63) / 64, (N_NODES + 255) / 256);   // (4, 196)
    int warpGrid = (N_NODES * 32 + 255) / 256;

    // launches 1-3: splits + init, 4th = layer-1 GEMM (ncu captures #4)
    k_splitX<<<(int)(((long)N_NODES * K2_IN + 255) / 256), 256>>>(x);
    k_splitW<<<(5 * HC * W_ST + 255) / 256, 256>>>(W[0], W[1], W[2], W[3], W[4]);
    k_init_cnt<<<(G_GRAPHS * HC + 255) / 256, 256>>>();
    k_gemm_pre<<<tg, 256, GEMM_SMEM>>>(pxh, pxl, K2_IN, pwh, pwl, W_ST,
                                       ph, N_NODES, K2_IN, HC);

    k_count<<<(E_EDGES + 255) / 256, 256>>>(ei);
    k_pcnt<<<(N_NODES + 255) / 256, 256>>>(batch);
    k_bsum<<<NB_SCAN, 256>>>();
    k_bscan<<<1, 32>>>();
    k_rowptr<<<NB_SCAN, 256>>>();
    k_scatter<<<(E_TOT + 255) / 256, 256>>>(ei);

    k_scores<<<warpGrid, 256>>>(as_[0], ad_[0]);
    k_aggregate<<<warpGrid, 256>>>(bc_[0], 0);

    for (int l = 1; l < 5; l++) {
        k_gemm_pre<<<tg, 256, GEMM_SMEM>>>(pah, pal, K2_HID,
                                           pwh + l * HC * W_ST, pwl + l * HC * W_ST, W_ST,
                                           ph, N_NODES, K2_HID, HC);
        k_scores<<<warpGrid, 256>>>(as_[l], ad_[l]);
        k_aggregate<<<warpGrid, 256>>>(bc_[l], l == 4 ? 1 : 0);
    }

    k_pool<<<(N_NODES * HC + 255) / 256, 256>>>(batch);

    k_mlp<<<G_GRAPHS, 128>>>(ppool, lw1, lb1, pt1, 200, 100, 1, 1);
    k_mlp<<<G_GRAPHS, 128>>>(pt1, lw2, lb2, pt2, 100, 100, 1, 0);
    k_mlp<<<G_GRAPHS, 128>>>(pt2, lw3, lb3, (float*)d_out, 100, 29, 0, 0);
}

// round 16
// speedup vs baseline: 1.1199x; 1.1199x over previous
#include <cuda_runtime.h>
#include <cuda_bf16.h>
#include <cstdint>

#define N_NODES 50000
#define E_EDGES 400000
#define E_TOT   450000
#define G_GRAPHS 256
#define HC 200
#define C_CH 100
#define F_IN 336
#define SLOPE 0.2f
#define NB_SCAN 49

// ---------------- scratch ------------------------------------------------------
__device__ float g_x[N_NODES * HC];
__device__ float g_h[N_NODES * HC];
__device__ float g_es[N_NODES * 2];
__device__ float g_ed[N_NODES * 2];
__device__ float g_alpha[E_TOT * 2];
__device__ int   g_cnt[N_NODES];
__device__ int   g_rowptr[N_NODES + 1];
__device__ int   g_wr[N_NODES];
__device__ int   g_srcidx[E_TOT];
__device__ int   g_bsum[NB_SCAN];
__device__ float g_pool[G_GRAPHS * HC];
__device__ int   g_pcnt[G_GRAPHS];
__device__ float g_t1[G_GRAPHS * 100];
__device__ float g_t2[G_GRAPHS * 100];

// ---------------- CSR build ----------------------------------------------------
__global__ void k_init_cnt() {
    int i = blockIdx.x * blockDim.x + threadIdx.x;
    if (i < N_NODES) g_cnt[i] = 1;
    if (i < G_GRAPHS) g_pcnt[i] = 0;
    if (i < G_GRAPHS * HC) g_pool[i] = 0.f;
}

__global__ void k_count(const int* __restrict__ ei) {
    int e = blockIdx.x * blockDim.x + threadIdx.x;
    if (e < E_EDGES) atomicAdd(&g_cnt[ei[E_EDGES + e]], 1);
}

__global__ void k_pcnt(const int* __restrict__ batch) {
    int i = blockIdx.x * blockDim.x + threadIdx.x;
    if (i < N_NODES) atomicAdd(&g_pcnt[batch[i]], 1);
}

__global__ void k_bsum() {
    __shared__ int sh[256];
    int b = blockIdx.x, t = threadIdx.x;
    int base = b * 1024;
    int s = 0;
#pragma unroll
    for (int j = 0; j < 4; j++) {
        int i = base + t + j * 256;
        if (i < N_NODES) s += g_cnt[i];
    }
    sh[t] = s; __syncthreads();
    for (int off = 128; off; off >>= 1) {
        if (t < off) sh[t] += sh[t + off];
        __syncthreads();
    }
    if (t == 0) g_bsum[b] = sh[0];
}

__global__ void k_bscan() {
    if (threadIdx.x == 0) {
        int run = 0;
        for (int b = 0; b < NB_SCAN; b++) { int v = g_bsum[b]; g_bsum[b] = run; run += v; }
    }
}

__global__ void k_rowptr() {
    __shared__ int sh[256];
    int b = blockIdx.x, t = threadIdx.x;
    int i0 = b * 1024 + t * 4;
    int c[4]; int local = 0;
#pragma unroll
    for (int j = 0; j < 4; j++) {
        int i = i0 + j;
        c[j] = (i < N_NODES) ? g_cnt[i] : 0;
        local += c[j];
    }
    sh[t] = local; __syncthreads();
    for (int off = 1; off < 256; off <<= 1) {
        int v = (t >= off) ? sh[t - off] : 0;
        __syncthreads();
        sh[t] += v;
        __syncthreads();
    }
    int run = g_bsum[b] + sh[t] - local;
#pragma unroll
    for (int j = 0; j < 4; j++) {
        int i = i0 + j;
        if (i < N_NODES) { g_rowptr[i] = run; g_wr[i] = run; run += c[j]; }
    }
    if (b == 0 && t == 0) g_rowptr[N_NODES] = E_TOT;
}

__global__ void k_scatter(const int* __restrict__ ei) {
    int e = blockIdx.x * blockDim.x + threadIdx.x;
    if (e >= E_TOT) return;
    int s, d;
    if (e < E_EDGES) { s = ei[e]; d = ei[E_EDGES + e]; }
    else             { s = d = e - E_EDGES; }
    int pos = atomicAdd(&g_wr[d], 1);
    g_srcidx[pos] = s;
}

// ---------------- bf16x3 tensor-core GEMM with ldmatrix (R9 proven) ------------
__device__ __forceinline__ uint32_t pack_bf16(float lo_e, float hi_e) {
    uint32_t u;
    asm("cvt.rn.bf16x2.f32 %0, %1, %2;" : "=r"(u) : "f"(hi_e), "f"(lo_e));
    return u;
}
__device__ __forceinline__ float bf16lo_f(uint32_t u) { return __uint_as_float(u << 16); }
__device__ __forceinline__ float bf16hi_f(uint32_t u) { return __uint_as_float(u & 0xFFFF0000u); }
__device__ __forceinline__ void split_pair(float x0, float x1, uint32_t& hi, uint32_t& lo) {
    hi = pack_bf16(x0, x1);
    float r0 = x0 - bf16lo_f(hi);
    float r1 = x1 - bf16hi_f(hi);
    lo = pack_bf16(r0, r1);
}

__device__ __forceinline__ void mma_bf16(float* c, const uint32_t* a, const uint32_t* b) {
    asm volatile(
        "mma.sync.aligned.m16n8k16.row.col.f32.bf16.bf16.f32 "
        "{%0,%1,%2,%3},{%4,%5,%6,%7},{%8,%9},{%0,%1,%2,%3};"
        : "+f"(c[0]), "+f"(c[1]), "+f"(c[2]), "+f"(c[3])
        : "r"(a[0]), "r"(a[1]), "r"(a[2]), "r"(a[3]), "r"(b[0]), "r"(b[1]));
}

__device__ __forceinline__ void ldm_x4(uint32_t& r0, uint32_t& r1, uint32_t& r2,
                                       uint32_t& r3, uint32_t addr) {
    asm volatile("ldmatrix.sync.aligned.m8n8.x4.shared.b16 {%0,%1,%2,%3}, [%4];"
                 : "=r"(r0), "=r"(r1), "=r"(r2), "=r"(r3) : "r"(addr));
}

#define PST 20   // uint32 per smem row (80B) -> ldmatrix conflict-free

__global__ void __launch_bounds__(256, 2)
k_gemm_bf16x3(const float* __restrict__ A, const float* __restrict__ B,
              float* __restrict__ C, int M, int K, int Nn)
{
    __shared__ __align__(16) uint32_t AsH[128][PST], AsL[128][PST];
    __shared__ __align__(16) uint32_t BsH[64][PST],  BsL[64][PST];

    int tid = threadIdx.x;
    int rowBase = blockIdx.y * 128;
    int colBase = blockIdx.x * 64;
    int warpId = tid >> 5, lane = tid & 31;
    int wm = (warpId & 3) * 32;
    int wn = (warpId >> 2) * 32;
    int gr = lane >> 2;
    int cq = lane & 3;
    int lrow = lane & 15;
    int lcol = (lane >> 4) * 4;

    uint32_t aHi = (uint32_t)__cvta_generic_to_shared(&AsH[0][0]);
    uint32_t aLo = (uint32_t)__cvta_generic_to_shared(&AsL[0][0]);
    uint32_t bHi = (uint32_t)__cvta_generic_to_shared(&BsH[0][0]);
    uint32_t bLo = (uint32_t)__cvta_generic_to_shared(&BsL[0][0]);

    float acc[2][4][4];
#pragma unroll
    for (int i = 0; i < 2; i++)
#pragma unroll
        for (int j = 0; j < 4; j++)
#pragma unroll
            for (int k = 0; k < 4; k++) acc[i][j][k] = 0.f;

    int am  = tid >> 2;          // 0..63
    int ak8 = (tid & 3) * 8;     // 0,8,16,24
    int bn  = tid & 63;          // 0..63
    int bk8 = (tid >> 6) * 8;    // 0,8,16,24

    int ntiles = (K + 31) / 32;

    float4 ra[2][2];
    float rbv[8];

    auto load_tile = [&](int t) {
        int k0 = t * 32;
#pragma unroll
        for (int i = 0; i < 2; i++) {
            int gm = rowBase + am + i * 64;
#pragma unroll
            for (int j = 0; j < 2; j++) {
                int gk = k0 + ak8 + j * 4;
                ra[i][j] = make_float4(0.f, 0.f, 0.f, 0.f);
                if (gm < M && gk < K)
                    ra[i][j] = *(const float4*)(A + (long)gm * K + gk);
            }
        }
        int gn = colBase + bn;
#pragma unroll
        for (int i = 0; i < 8; i++) {
            int gk = k0 + bk8 + i;
            rbv[i] = 0.f;
            if (gk < K && gn < Nn) rbv[i] = B[(long)gk * Nn + gn];
        }
    };

    load_tile(0);

    for (int t = 0; t < ntiles; t++) {
#pragma unroll
        for (int i = 0; i < 2; i++) {
            int m = am + i * 64;
            const float* p = &ra[i][0].x;
            uint32_t h[4], l[4];
#pragma unroll
            for (int w = 0; w < 4; w++) split_pair(p[2 * w], p[2 * w + 1], h[w], l[w]);
            *(uint4*)&AsH[m][ak8 >> 1] = make_uint4(h[0], h[1], h[2], h[3]);
            *(uint4*)&AsL[m][ak8 >> 1] = make_uint4(l[0], l[1], l[2], l[3]);
        }
        {
            uint32_t h[4], l[4];
#pragma unroll
            for (int q = 0; q < 4; q++) split_pair(rbv[2 * q], rbv[2 * q + 1], h[q], l[q]);
            *(uint4*)&BsH[bn][bk8 >> 1] = make_uint4(h[0], h[1], h[2], h[3]);
            *(uint4*)&BsL[bn][bk8 >> 1] = make_uint4(l[0], l[1], l[2], l[3]);
        }
        __syncthreads();

        if (t + 1 < ntiles) load_tile(t + 1);

#pragma unroll
        for (int ks = 0; ks < 2; ks++) {
            int kc = ks * 8 + lcol;
            uint32_t ah[2][4], al_[2][4];
#pragma unroll
            for (int mt = 0; mt < 2; mt++) {
                uint32_t off = (uint32_t)((wm + mt * 16 + lrow) * PST + kc) * 4;
                ldm_x4(ah[mt][0], ah[mt][1], ah[mt][2], ah[mt][3], aHi + off);
                ldm_x4(al_[mt][0], al_[mt][1], al_[mt][2], al_[mt][3], aLo + off);
            }
            uint32_t bh[4][2], bl[4][2];
#pragma unroll
            for (int nb = 0; nb < 2; nb++) {
                uint32_t off = (uint32_t)((wn + nb * 16 + lrow) * PST + kc) * 4;
                uint32_t t0, t1, t2, t3;
                ldm_x4(t0, t1, t2, t3, bHi + off);
                bh[2 * nb][0] = t0; bh[2 * nb][1] = t2;
                bh[2 * nb + 1][0] = t1; bh[2 * nb + 1][1] = t3;
                ldm_x4(t0, t1, t2, t3, bLo + off);
                bl[2 * nb][0] = t0; bl[2 * nb][1] = t2;
                bl[2 * nb + 1][0] = t1; bl[2 * nb + 1][1] = t3;
            }
#pragma unroll
            for (int mt = 0; mt < 2; mt++)
#pragma unroll
                for (int nt = 0; nt < 4; nt++) {
                    float* c = acc[mt][nt];
                    mma_bf16(c, al_[mt], bh[nt]);
                    mma_bf16(c, ah[mt], bl[nt]);
                    mma_bf16(c, ah[mt], bh[nt]);
                }
        }
        __syncthreads();
    }

#pragma unroll
    for (int mt = 0; mt < 2; mt++) {
#pragma unroll
        for (int nt = 0; nt < 4; nt++) {
            int row = rowBase + wm + mt * 16 + gr;
            int col = colBase + wn + nt * 8 + cq * 2;
            float* c = acc[mt][nt];
            if (col < Nn) {
                if (row < M)
                    *(float2*)(C + (long)row * Nn + col) = make_float2(c[0], c[1]);
                if (row + 8 < M)
                    *(float2*)(C + (long)(row + 8) * Nn + col) = make_float2(c[2], c[3]);
            }
        }
    }
}

// ---------------- attention scores (warp per node) -----------------------------
__global__ void k_scores(const float* __restrict__ asrc, const float* __restrict__ adst) {
    int gwarp = (blockIdx.x * blockDim.x + threadIdx.x) >> 5;
    int lane  = threadIdx.x & 31;
    if (gwarp >= N_NODES) return;
    const float* hr = g_h + (long)gwarp * HC;
    float es0 = 0.f, es1 = 0.f, ed0 = 0.f, ed1 = 0.f;
    for (int c = lane; c < HC; c += 32) {
        float v = hr[c], a = asrc[c], d = adst[c];
        if (c < C_CH) { es0 += v * a; ed0 += v * d; }
        else          { es1 += v * a; ed1 += v * d; }
    }
#pragma unroll
    for (int o = 16; o; o >>= 1) {
        es0 += __shfl_xor_sync(0xffffffffu, es0, o);
        es1 += __shfl_xor_sync(0xffffffffu, es1, o);
        ed0 += __shfl_xor_sync(0xffffffffu, ed0, o);
        ed1 += __shfl_xor_sync(0xffffffffu, ed1, o);
    }
    if (lane == 0) {
        g_es[gwarp * 2]     = es0;
        g_es[gwarp * 2 + 1] = es1;
        g_ed[gwarp * 2]     = ed0;
        g_ed[gwarp * 2 + 1] = ed1;
    }
}

// ---------------- softmax + aggregate + bias + relu (warp per dst) -------------
// pass 1 gathers scores once and caches lrelu(e) in g_alpha (coalesced);
// pass 2 reads the cache coalesced instead of re-gathering g_es.
__device__ __forceinline__ float lrelu(float e) { return e > 0.f ? e : SLOPE * e; }

__global__ void k_aggregate(const float* __restrict__ bc) {
    int gwarp = (blockIdx.x * blockDim.x + threadIdx.x) >> 5;
    int lane  = threadIdx.x & 31;
    if (gwarp >= N_NODES) return;
    int dst = gwarp;
    int beg = g_rowptr[dst], end = g_rowptr[dst + 1];
    float ed0 = g_ed[dst * 2], ed1 = g_ed[dst * 2 + 1];

    float m0 = -1e30f, m1 = -1e30f;
    for (int i = beg + lane; i < end; i += 32) {
        int s = g_srcidx[i];
        float e0 = lrelu(g_es[s * 2]     + ed0);
        float e1 = lrelu(g_es[s * 2 + 1] + ed1);
        g_alpha[i * 2]     = e0;
        g_alpha[i * 2 + 1] = e1;
        m0 = fmaxf(m0, e0);
        m1 = fmaxf(m1, e1);
    }
#pragma unroll
    for (int o = 16; o; o >>= 1) {
        m0 = fmaxf(m0, __shfl_xor_sync(0xffffffffu, m0, o));
        m1 = fmaxf(m1, __shfl_xor_sync(0xffffffffu, m1, o));
    }

    float s0 = 0.f, s1 = 0.f;
    for (int i = beg + lane; i < end; i += 32) {
        float p0 = __expf(g_alpha[i * 2]     - m0);
        float p1 = __expf(g_alpha[i * 2 + 1] - m1);
        g_alpha[i * 2]     = p0;
        g_alpha[i * 2 + 1] = p1;
        s0 += p0; s1 += p1;
    }
#pragma unroll
    for (int o = 16; o; o >>= 1) {
        s0 += __shfl_xor_sync(0xffffffffu, s0, o);
        s1 += __shfl_xor_sync(0xffffffffu, s1, o);
    }
    float inv0 = 1.f / (s0 + 1e-16f);
    float inv1 = 1.f / (s1 + 1e-16f);

    float acc[7] = {0.f, 0.f, 0.f, 0.f, 0.f, 0.f, 0.f};
    for (int i = beg; i < end; i++) {
        int s = g_srcidx[i];
        float a0 = g_alpha[i * 2]     * inv0;
        float a1 = g_alpha[i * 2 + 1] * inv1;
        const float* hr = g_h + (long)s * HC;
#pragma unroll
        for (int k = 0; k < 7; k++) {
            int c = lane + k * 32;
            if (c < HC) acc[k] += (c < C_CH ? a0 : a1) * hr[c];
        }
    }
#pragma unroll
    for (int k = 0; k < 7; k++) {
        int c = lane + k * 32;
        if (c < HC) g_x[(long)dst * HC + c] = fmaxf(acc[k] + bc[c], 0.f);
    }
}

// ---------------- mean pool ----------------------------------------------------
__global__ void k_pool(const int* __restrict__ batch) {
    int i = blockIdx.x * blockDim.x + threadIdx.x;
    if (i >= N_NODES * HC) return;
    int n = i / HC, c = i - n * HC;
    int b = batch[n];
    atomicAdd(&g_pool[b * HC + c], g_x[i]);
}

// ---------------- tiny MLP layer -----------------------------------------------
__global__ void k_mlp(const float* __restrict__ A, const float* __restrict__ Wm,
                      const float* __restrict__ bm, float* __restrict__ out,
                      int K, int Nn, int do_relu, int do_div) {
    int g = blockIdx.x;
    __shared__ float arow[HC];
    float inv = 1.f;
    if (do_div) inv = 1.f / fmaxf((float)g_pcnt[g], 1.f);
    for (int i = threadIdx.x; i < K; i += blockDim.x) arow[i] = A[g * K + i] * inv;
    __syncthreads();
    for (int j = threadIdx.x; j < Nn; j += blockDim.x) {
        float acc = bm[j];
        for (int k = 0; k < K; k++) acc += arow[k] * Wm[k * Nn + j];
        if (do_relu) acc = fmaxf(acc, 0.f);
        out[g * Nn + j] = acc;
    }
}

// ---------------- launch --------------------------------------------------------
extern "C" void kernel_launch(void* const* d_in, const int* in_sizes, int n_in,
                              void* d_out, int out_size) {
    const float* x    = (const float*)d_in[0];
    const int*   ei   = (const int*)d_in[1];
    const int*   batch= (const int*)d_in[2];
    const float *W[5], *as_[5], *ad_[5], *bc_[5];
    for (int i = 0; i < 5; i++) {
        W[i]   = (const float*)d_in[3 + 4 * i];
        as_[i] = (const float*)d_in[4 + 4 * i];
        ad_[i] = (const float*)d_in[5 + 4 * i];
        bc_[i] = (const float*)d_in[6 + 4 * i];
    }
    const float* lw1 = (const float*)d_in[23];
    const float* lb1 = (const float*)d_in[24];
    const float* lw2 = (const float*)d_in[25];
    const float* lb2 = (const float*)d_in[26];
    const float* lw3 = (const float*)d_in[27];
    const float* lb3 = (const float*)d_in[28];

    float *px, *ph, *ppool, *pt1, *pt2;
    cudaGetSymbolAddress((void**)&px, g_x);
    cudaGetSymbolAddress((void**)&ph, g_h);
    cudaGetSymbolAddress((void**)&ppool, g_pool);
    cudaGetSymbolAddress((void**)&pt1, g_t1);
    cudaGetSymbolAddress((void**)&pt2, g_t2);

    dim3 ggrid((HC + 63) / 64, (N_NODES + 127) / 128);
    int warpGrid = (N_NODES * 32 + 255) / 256;

    // launches 1-3: CSR prep, 4th = layer-1 GEMM (ncu captures #4)
    k_init_cnt<<<(G_GRAPHS * HC + 255) / 256, 256>>>();
    k_count<<<(E_EDGES + 255) / 256, 256>>>(ei);
    k_pcnt<<<(N_NODES + 255) / 256, 256>>>(batch);
    k_gemm_bf16x3<<<ggrid, 256>>>(x, W[0], ph, N_NODES, F_IN, HC);

    k_bsum<<<NB_SCAN, 256>>>();
    k_bscan<<<1, 32>>>();
    k_rowptr<<<NB_SCAN, 256>>>();
    k_scatter<<<(E_TOT + 255) / 256, 256>>>(ei);

    k_scores<<<warpGrid, 256>>>(as_[0], ad_[0]);
    k_aggregate<<<warpGrid, 256>>>(bc_[0]);

    for (int l = 1; l < 5; l++) {
        k_gemm_bf16x3<<<ggrid, 256>>>(px, W[l], ph, N_NODES, HC, HC);
        k_scores<<<warpGrid, 256>>>(as_[l], ad_[l]);
        k_aggregate<<<warpGrid, 256>>>(bc_[l]);
    }

    k_pool<<<(N_NODES * HC + 255) / 256, 256>>>(batch);

    k_mlp<<<G_GRAPHS, 128>>>(ppool, lw1, lb1, pt1, 200, 100, 1, 1);
    k_mlp<<<G_GRAPHS, 128>>>(pt1, lw2, lb2, pt2, 100, 100, 1, 0);
    k_mlp<<<G_GRAPHS, 128>>>(pt2, lw3, lb3, (float*)d_out, 100, 29, 0, 0);
}

// round 17
// speedup vs baseline: 1.2060x; 1.0769x over previous
#include <cuda_runtime.h>
#include <cuda_bf16.h>
#include <cstdint>

#define N_NODES 50000
#define E_EDGES 400000
#define E_TOT   450000
#define G_GRAPHS 256
#define HC 200
#define C_CH 100
#define F_IN 336
#define SLOPE 0.2f
#define NB_SCAN 49

// ---------------- scratch ------------------------------------------------------
__device__ float g_x[N_NODES * HC];
__device__ float g_h[N_NODES * HC];
__device__ float g_es[N_NODES * 2];
__device__ float g_ed[N_NODES * 2];
__device__ float g_alpha[E_TOT * 2];
__device__ int   g_cnt[N_NODES];
__device__ int   g_rowptr[N_NODES + 1];
__device__ int   g_wr[N_NODES];
__device__ int   g_srcidx[E_TOT];
__device__ int   g_bsum[NB_SCAN];
__device__ float g_pool[G_GRAPHS * HC];
__device__ int   g_pcnt[G_GRAPHS];
__device__ int   g_goff[G_GRAPHS + 1];
__device__ float g_t1[G_GRAPHS * 100];
__device__ float g_t2[G_GRAPHS * 100];

// ---------------- CSR build ----------------------------------------------------
__global__ void k_init_cnt() {
    int i = blockIdx.x * blockDim.x + threadIdx.x;
    if (i < N_NODES) g_cnt[i] = 1;
    if (i < G_GRAPHS) g_pcnt[i] = 0;
}

__global__ void k_count(const int* __restrict__ ei) {
    int e = blockIdx.x * blockDim.x + threadIdx.x;
    if (e < E_EDGES) atomicAdd(&g_cnt[ei[E_EDGES + e]], 1);
}

__global__ void k_pcnt(const int* __restrict__ batch) {
    int i = blockIdx.x * blockDim.x + threadIdx.x;
    if (i < N_NODES) atomicAdd(&g_pcnt[batch[i]], 1);
}

__global__ void k_goff() {   // prefix over 256 graph counts (batch is sorted)
    if (threadIdx.x == 0) {
        int run = 0;
        for (int g = 0; g < G_GRAPHS; g++) { g_goff[g] = run; run += g_pcnt[g]; }
        g_goff[G_GRAPHS] = run;
    }
}

__global__ void k_bsum() {
    __shared__ int sh[256];
    int b = blockIdx.x, t = threadIdx.x;
    int base = b * 1024;
    int s = 0;
#pragma unroll
    for (int j = 0; j < 4; j++) {
        int i = base + t + j * 256;
        if (i < N_NODES) s += g_cnt[i];
    }
    sh[t] = s; __syncthreads();
    for (int off = 128; off; off >>= 1) {
        if (t < off) sh[t] += sh[t + off];
        __syncthreads();
    }
    if (t == 0) g_bsum[b] = sh[0];
}

__global__ void k_bscan() {
    if (threadIdx.x == 0) {
        int run = 0;
        for (int b = 0; b < NB_SCAN; b++) { int v = g_bsum[b]; g_bsum[b] = run; run += v; }
    }
}

__global__ void k_rowptr() {
    __shared__ int sh[256];
    int b = blockIdx.x, t = threadIdx.x;
    int i0 = b * 1024 + t * 4;
    int c[4]; int local = 0;
#pragma unroll
    for (int j = 0; j < 4; j++) {
        int i = i0 + j;
        c[j] = (i < N_NODES) ? g_cnt[i] : 0;
        local += c[j];
    }
    sh[t] = local; __syncthreads();
    for (int off = 1; off < 256; off <<= 1) {
        int v = (t >= off) ? sh[t - off] : 0;
        __syncthreads();
        sh[t] += v;
        __syncthreads();
    }
    int run = g_bsum[b] + sh[t] - local;
#pragma unroll
    for (int j = 0; j < 4; j++) {
        int i = i0 + j;
        if (i < N_NODES) { g_rowptr[i] = run; g_wr[i] = run; run += c[j]; }
    }
    if (b == 0 && t == 0) g_rowptr[N_NODES] = E_TOT;
}

__global__ void k_scatter(const int* __restrict__ ei) {
    int e = blockIdx.x * blockDim.x + threadIdx.x;
    if (e >= E_TOT) return;
    int s, d;
    if (e < E_EDGES) { s = ei[e]; d = ei[E_EDGES + e]; }
    else             { s = d = e - E_EDGES; }
    int pos = atomicAdd(&g_wr[d], 1);
    g_srcidx[pos] = s;
}

// ---------------- bf16x3 tensor-core GEMM with ldmatrix (R9 proven) ------------
__device__ __forceinline__ uint32_t pack_bf16(float lo_e, float hi_e) {
    uint32_t u;
    asm("cvt.rn.bf16x2.f32 %0, %1, %2;" : "=r"(u) : "f"(hi_e), "f"(lo_e));
    return u;
}
__device__ __forceinline__ float bf16lo_f(uint32_t u) { return __uint_as_float(u << 16); }
__device__ __forceinline__ float bf16hi_f(uint32_t u) { return __uint_as_float(u & 0xFFFF0000u); }
__device__ __forceinline__ void split_pair(float x0, float x1, uint32_t& hi, uint32_t& lo) {
    hi = pack_bf16(x0, x1);
    float r0 = x0 - bf16lo_f(hi);
    float r1 = x1 - bf16hi_f(hi);
    lo = pack_bf16(r0, r1);
}

__device__ __forceinline__ void mma_bf16(float* c, const uint32_t* a, const uint32_t* b) {
    asm volatile(
        "mma.sync.aligned.m16n8k16.row.col.f32.bf16.bf16.f32 "
        "{%0,%1,%2,%3},{%4,%5,%6,%7},{%8,%9},{%0,%1,%2,%3};"
        : "+f"(c[0]), "+f"(c[1]), "+f"(c[2]), "+f"(c[3])
        : "r"(a[0]), "r"(a[1]), "r"(a[2]), "r"(a[3]), "r"(b[0]), "r"(b[1]));
}

__device__ __forceinline__ void ldm_x4(uint32_t& r0, uint32_t& r1, uint32_t& r2,
                                       uint32_t& r3, uint32_t addr) {
    asm volatile("ldmatrix.sync.aligned.m8n8.x4.shared.b16 {%0,%1,%2,%3}, [%4];"
                 : "=r"(r0), "=r"(r1), "=r"(r2), "=r"(r3) : "r"(addr));
}

#define PST 20   // uint32 per smem row (80B) -> ldmatrix conflict-free

__global__ void __launch_bounds__(256, 2)
k_gemm_bf16x3(const float* __restrict__ A, const float* __restrict__ B,
              float* __restrict__ C, int M, int K, int Nn)
{
    __shared__ __align__(16) uint32_t AsH[128][PST], AsL[128][PST];
    __shared__ __align__(16) uint32_t BsH[64][PST],  BsL[64][PST];

    int tid = threadIdx.x;
    int rowBase = blockIdx.y * 128;
    int colBase = blockIdx.x * 64;
    int warpId = tid >> 5, lane = tid & 31;
    int wm = (warpId & 3) * 32;
    int wn = (warpId >> 2) * 32;
    int gr = lane >> 2;
    int cq = lane & 3;
    int lrow = lane & 15;
    int lcol = (lane >> 4) * 4;

    uint32_t aHi = (uint32_t)__cvta_generic_to_shared(&AsH[0][0]);
    uint32_t aLo = (uint32_t)__cvta_generic_to_shared(&AsL[0][0]);
    uint32_t bHi = (uint32_t)__cvta_generic_to_shared(&BsH[0][0]);
    uint32_t bLo = (uint32_t)__cvta_generic_to_shared(&BsL[0][0]);

    float acc[2][4][4];
#pragma unroll
    for (int i = 0; i < 2; i++)
#pragma unroll
        for (int j = 0; j < 4; j++)
#pragma unroll
            for (int k = 0; k < 4; k++) acc[i][j][k] = 0.f;

    int am  = tid >> 2;          // 0..63
    int ak8 = (tid & 3) * 8;     // 0,8,16,24
    int bn  = tid & 63;          // 0..63
    int bk8 = (tid >> 6) * 8;    // 0,8,16,24

    int ntiles = (K + 31) / 32;

    float4 ra[2][2];
    float rbv[8];

    auto load_tile = [&](int t) {
        int k0 = t * 32;
#pragma unroll
        for (int i = 0; i < 2; i++) {
            int gm = rowBase + am + i * 64;
#pragma unroll
            for (int j = 0; j < 2; j++) {
                int gk = k0 + ak8 + j * 4;
                ra[i][j] = make_float4(0.f, 0.f, 0.f, 0.f);
                if (gm < M && gk < K)
                    ra[i][j] = *(const float4*)(A + (long)gm * K + gk);
            }
        }
        int gn = colBase + bn;
#pragma unroll
        for (int i = 0; i < 8; i++) {
            int gk = k0 + bk8 + i;
            rbv[i] = 0.f;
            if (gk < K && gn < Nn) rbv[i] = B[(long)gk * Nn + gn];
        }
    };

    load_tile(0);

    for (int t = 0; t < ntiles; t++) {
#pragma unroll
        for (int i = 0; i < 2; i++) {
            int m = am + i * 64;
            const float* p = &ra[i][0].x;
            uint32_t h[4], l[4];
#pragma unroll
            for (int w = 0; w < 4; w++) split_pair(p[2 * w], p[2 * w + 1], h[w], l[w]);
            *(uint4*)&AsH[m][ak8 >> 1] = make_uint4(h[0], h[1], h[2], h[3]);
            *(uint4*)&AsL[m][ak8 >> 1] = make_uint4(l[0], l[1], l[2], l[3]);
        }
        {
            uint32_t h[4], l[4];
#pragma unroll
            for (int q = 0; q < 4; q++) split_pair(rbv[2 * q], rbv[2 * q + 1], h[q], l[q]);
            *(uint4*)&BsH[bn][bk8 >> 1] = make_uint4(h[0], h[1], h[2], h[3]);
            *(uint4*)&BsL[bn][bk8 >> 1] = make_uint4(l[0], l[1], l[2], l[3]);
        }
        __syncthreads();

        if (t + 1 < ntiles) load_tile(t + 1);

#pragma unroll
        for (int ks = 0; ks < 2; ks++) {
            int kc = ks * 8 + lcol;
            uint32_t ah[2][4], al_[2][4];
#pragma unroll
            for (int mt = 0; mt < 2; mt++) {
                uint32_t off = (uint32_t)((wm + mt * 16 + lrow) * PST + kc) * 4;
                ldm_x4(ah[mt][0], ah[mt][1], ah[mt][2], ah[mt][3], aHi + off);
                ldm_x4(al_[mt][0], al_[mt][1], al_[mt][2], al_[mt][3], aLo + off);
            }
            uint32_t bh[4][2], bl[4][2];
#pragma unroll
            for (int nb = 0; nb < 2; nb++) {
                uint32_t off = (uint32_t)((wn + nb * 16 + lrow) * PST + kc) * 4;
                uint32_t t0, t1, t2, t3;
                ldm_x4(t0, t1, t2, t3, bHi + off);
                bh[2 * nb][0] = t0; bh[2 * nb][1] = t2;
                bh[2 * nb + 1][0] = t1; bh[2 * nb + 1][1] = t3;
                ldm_x4(t0, t1, t2, t3, bLo + off);
                bl[2 * nb][0] = t0; bl[2 * nb][1] = t2;
                bl[2 * nb + 1][0] = t1; bl[2 * nb + 1][1] = t3;
            }
#pragma unroll
            for (int mt = 0; mt < 2; mt++)
#pragma unroll
                for (int nt = 0; nt < 4; nt++) {
                    float* c = acc[mt][nt];
                    mma_bf16(c, al_[mt], bh[nt]);
                    mma_bf16(c, ah[mt], bl[nt]);
                    mma_bf16(c, ah[mt], bh[nt]);
                }
        }
        __syncthreads();
    }

#pragma unroll
    for (int mt = 0; mt < 2; mt++) {
#pragma unroll
        for (int nt = 0; nt < 4; nt++) {
            int row = rowBase + wm + mt * 16 + gr;
            int col = colBase + wn + nt * 8 + cq * 2;
            float* c = acc[mt][nt];
            if (col < Nn) {
                if (row < M)
                    *(float2*)(C + (long)row * Nn + col) = make_float2(c[0], c[1]);
                if (row + 8 < M)
                    *(float2*)(C + (long)(row + 8) * Nn + col) = make_float2(c[2], c[3]);
            }
        }
    }
}

// ---------------- attention scores (warp per node, float4) ---------------------
__global__ void k_scores(const float* __restrict__ asrc, const float* __restrict__ adst) {
    int gwarp = (blockIdx.x * blockDim.x + threadIdx.x) >> 5;
    int lane  = threadIdx.x & 31;
    if (gwarp >= N_NODES) return;
    const float4* hr = (const float4*)(g_h + (long)gwarp * HC);
    const float4* a4 = (const float4*)asrc;
    const float4* d4 = (const float4*)adst;
    float es0 = 0.f, es1 = 0.f, ed0 = 0.f, ed1 = 0.f;
#pragma unroll
    for (int k = 0; k < 2; k++) {
        int p = lane + k * 32;          // float4 index; 50 total, head split at 25
        if (p < 50) {
            float4 v = hr[p], a = a4[p], d = d4[p];
            float s = v.x * a.x + v.y * a.y + v.z * a.z + v.w * a.w;
            float t = v.x * d.x + v.y * d.y + v.z * d.z + v.w * d.w;
            if (p < 25) { es0 += s; ed0 += t; }
            else        { es1 += s; ed1 += t; }
        }
    }
#pragma unroll
    for (int o = 16; o; o >>= 1) {
        es0 += __shfl_xor_sync(0xffffffffu, es0, o);
        es1 += __shfl_xor_sync(0xffffffffu, es1, o);
        ed0 += __shfl_xor_sync(0xffffffffu, ed0, o);
        ed1 += __shfl_xor_sync(0xffffffffu, ed1, o);
    }
    if (lane == 0) {
        g_es[gwarp * 2]     = es0;
        g_es[gwarp * 2 + 1] = es1;
        g_ed[gwarp * 2]     = ed0;
        g_ed[gwarp * 2 + 1] = ed1;
    }
}

// ---------------- softmax + aggregate + bias + relu (R9 proven) ----------------
__device__ __forceinline__ float lrelu(float e) { return e > 0.f ? e : SLOPE * e; }

__global__ void k_aggregate(const float* __restrict__ bc) {
    int gwarp = (blockIdx.x * blockDim.x + threadIdx.x) >> 5;
    int lane  = threadIdx.x & 31;
    if (gwarp >= N_NODES) return;
    int dst = gwarp;
    int beg = g_rowptr[dst], end = g_rowptr[dst + 1];
    float ed0 = g_ed[dst * 2], ed1 = g_ed[dst * 2 + 1];

    float m0 = -1e30f, m1 = -1e30f;
    for (int i = beg + lane; i < end; i += 32) {
        int s = g_srcidx[i];
        m0 = fmaxf(m0, lrelu(g_es[s * 2]     + ed0));
        m1 = fmaxf(m1, lrelu(g_es[s * 2 + 1] + ed1));
    }
#pragma unroll
    for (int o = 16; o; o >>= 1) {
        m0 = fmaxf(m0, __shfl_xor_sync(0xffffffffu, m0, o));
        m1 = fmaxf(m1, __shfl_xor_sync(0xffffffffu, m1, o));
    }

    float s0 = 0.f, s1 = 0.f;
    for (int i = beg + lane; i < end; i += 32) {
        int s = g_srcidx[i];
        float p0 = __expf(lrelu(g_es[s * 2]     + ed0) - m0);
        float p1 = __expf(lrelu(g_es[s * 2 + 1] + ed1) - m1);
        g_alpha[i * 2]     = p0;
        g_alpha[i * 2 + 1] = p1;
        s0 += p0; s1 += p1;
    }
#pragma unroll
    for (int o = 16; o; o >>= 1) {
        s0 += __shfl_xor_sync(0xffffffffu, s0, o);
        s1 += __shfl_xor_sync(0xffffffffu, s1, o);
    }
    float inv0 = 1.f / (s0 + 1e-16f);
    float inv1 = 1.f / (s1 + 1e-16f);

    float acc[7] = {0.f, 0.f, 0.f, 0.f, 0.f, 0.f, 0.f};
    for (int i = beg; i < end; i++) {
        int s = g_srcidx[i];
        float a0 = g_alpha[i * 2]     * inv0;
        float a1 = g_alpha[i * 2 + 1] * inv1;
        const float* hr = g_h + (long)s * HC;
#pragma unroll
        for (int k = 0; k < 7; k++) {
            int c = lane + k * 32;
            if (c < HC) acc[k] += (c < C_CH ? a0 : a1) * hr[c];
        }
    }
#pragma unroll
    for (int k = 0; k < 7; k++) {
        int c = lane + k * 32;
        if (c < HC) g_x[(long)dst * HC + c] = fmaxf(acc[k] + bc[c], 0.f);
    }
}

// ---------------- mean pool (atomic-free: batch is sorted) ---------------------
__global__ void k_pool2() {
    int g = blockIdx.x;
    int c = threadIdx.x;
    if (c >= HC) return;
    int beg = g_goff[g], end = g_goff[g + 1];
    float s = 0.f;
    for (int n = beg; n < end; n++) s += g_x[(long)n * HC + c];
    g_pool[g * HC + c] = s;
}

// ---------------- tiny MLP layer -----------------------------------------------
__global__ void k_mlp(const float* __restrict__ A, const float* __restrict__ Wm,
                      const float* __restrict__ bm, float* __restrict__ out,
                      int K, int Nn, int do_relu, int do_div) {
    int g = blockIdx.x;
    __shared__ float arow[HC];
    float inv = 1.f;
    if (do_div) inv = 1.f / fmaxf((float)g_pcnt[g], 1.f);
    for (int i = threadIdx.x; i < K; i += blockDim.x) arow[i] = A[g * K + i] * inv;
    __syncthreads();
    for (int j = threadIdx.x; j < Nn; j += blockDim.x) {
        float acc = bm[j];
        for (int k = 0; k < K; k++) acc += arow[k] * Wm[k * Nn + j];
        if (do_relu) acc = fmaxf(acc, 0.f);
        out[g * Nn + j] = acc;
    }
}

// ---------------- launch --------------------------------------------------------
extern "C" void kernel_launch(void* const* d_in, const int* in_sizes, int n_in,
                              void* d_out, int out_size) {
    const float* x    = (const float*)d_in[0];
    const int*   ei   = (const int*)d_in[1];
    const int*   batch= (const int*)d_in[2];
    const float *W[5], *as_[5], *ad_[5], *bc_[5];
    for (int i = 0; i < 5; i++) {
        W[i]   = (const float*)d_in[3 + 4 * i];
        as_[i] = (const float*)d_in[4 + 4 * i];
        ad_[i] = (const float*)d_in[5 + 4 * i];
        bc_[i] = (const float*)d_in[6 + 4 * i];
    }
    const float* lw1 = (const float*)d_in[23];
    const float* lb1 = (const float*)d_in[24];
    const float* lw2 = (const float*)d_in[25];
    const float* lb2 = (const float*)d_in[26];
    const float* lw3 = (const float*)d_in[27];
    const float* lb3 = (const float*)d_in[28];

    float *px, *ph, *ppool, *pt1, *pt2;
    cudaGetSymbolAddress((void**)&px, g_x);
    cudaGetSymbolAddress((void**)&ph, g_h);
    cudaGetSymbolAddress((void**)&ppool, g_pool);
    cudaGetSymbolAddress((void**)&pt1, g_t1);
    cudaGetSymbolAddress((void**)&pt2, g_t2);

    dim3 ggrid((HC + 63) / 64, (N_NODES + 127) / 128);
    int warpGrid = (N_NODES * 32 + 255) / 256;

    // launches 1-3: CSR prep, 4th = layer-1 GEMM (ncu captures #4)
    k_init_cnt<<<(N_NODES + 255) / 256, 256>>>();
    k_count<<<(E_EDGES + 255) / 256, 256>>>(ei);
    k_pcnt<<<(N_NODES + 255) / 256, 256>>>(batch);
    k_gemm_bf16x3<<<ggrid, 256>>>(x, W[0], ph, N_NODES, F_IN, HC);

    k_goff<<<1, 32>>>();
    k_bsum<<<NB_SCAN, 256>>>();
    k_bscan<<<1, 32>>>();
    k_rowptr<<<NB_SCAN, 256>>>();
    k_scatter<<<(E_TOT + 255) / 256, 256>>>(ei);

    k_scores<<<warpGrid, 256>>>(as_[0], ad_[0]);
    k_aggregate<<<warpGrid, 256>>>(bc_[0]);

    for (int l = 1; l < 5; l++) {
        k_gemm_bf16x3<<<ggrid, 256>>>(px, W[l], ph, N_NODES, HC, HC);
        k_scores<<<warpGrid, 256>>>(as_[l], ad_[l]);
        k_aggregate<<<warpGrid, 256>>>(bc_[l]);
    }

    k_pool2<<<G_GRAPHS, 256>>>();

    k_mlp<<<G_GRAPHS, 128>>>(ppool, lw1, lb1, pt1, 200, 100, 1, 1);
    k_mlp<<<G_GRAPHS, 128>>>(pt1, lw2, lb2, pt2, 100, 100, 1, 0);
    k_mlp<<<G_GRAPHS, 128>>>(pt2, lw3, lb3, (float*)d_out, 100, 29, 0, 0);
}